// round 13
// baseline (speedup 1.0000x reference)
#include <cuda_runtime.h>
#include <cuda_fp16.h>
#include <cstdint>

#define BATCH 4
#define SEQ   4096
#define EMBED 512
#define HEAD  64
#define NTOK  (BATCH * SEQ)
// C^-0.5 * log2(e): Q pre-scale so softmax uses raw ex2
#define QSC2  (0.04419417382415922f * 1.4426950408889634f)

#define NUNITS 640          // split-K work units (160 per batch)
#define NEG_INF __int_as_float(0xff800000)
#define ONES16  0x3C003C00u // (1.0h, 1.0h)

// ---------------- scratch (device globals) ----------------
__device__ __half gK16[NTOK * HEAD];   // [t][h]
__device__ __half gQ16[NTOK * HEAD];   // [t][h], pre-scaled by QSC2
__device__ __half gV16[NTOK * HEAD];   // [t][h]
__device__ __half gW16[192 * EMBED];   // [Wk;Wq;Wv] rows, fp16
__device__ __half gOp16[NUNITS * 64 * 64];  // partial O (unnormalized, fp16)
__device__ float  gLp[NUNITS * 64];         // partial l (fp32)

// ---------------- helpers ----------------
__device__ __forceinline__ uint32_t smem_u32(const void* p) {
    uint32_t a;
    asm("{ .reg .u64 t; cvta.to.shared.u64 t, %1; cvt.u32.u64 %0, t; }" : "=r"(a) : "l"(p));
    return a;
}
__device__ __forceinline__ void ldsm4(uint32_t* r, uint32_t addr) {
    asm volatile("ldmatrix.sync.aligned.m8n8.x4.shared.b16 {%0,%1,%2,%3}, [%4];"
                 : "=r"(r[0]), "=r"(r[1]), "=r"(r[2]), "=r"(r[3]) : "r"(addr));
}
__device__ __forceinline__ void ldsm4t(uint32_t* r, uint32_t addr) {
    asm volatile("ldmatrix.sync.aligned.m8n8.x4.trans.shared.b16 {%0,%1,%2,%3}, [%4];"
                 : "=r"(r[0]), "=r"(r[1]), "=r"(r[2]), "=r"(r[3]) : "r"(addr));
}
__device__ __forceinline__ void mma16816(float* c, const uint32_t* a, uint32_t b0, uint32_t b1) {
    asm volatile(
        "mma.sync.aligned.m16n8k16.row.col.f32.f16.f16.f32 "
        "{%0,%1,%2,%3}, {%4,%5,%6,%7}, {%8,%9}, {%0,%1,%2,%3};"
        : "+f"(c[0]), "+f"(c[1]), "+f"(c[2]), "+f"(c[3])
        : "r"(a[0]), "r"(a[1]), "r"(a[2]), "r"(a[3]), "r"(b0), "r"(b1));
}
// single-instruction fp32x2 -> half2 pack (low = a, high = b)
__device__ __forceinline__ uint32_t cvt2h(float a, float b) {
    uint32_t r;
    asm("cvt.rn.f16x2.f32 %0, %1, %2;" : "=r"(r) : "f"(b), "f"(a));
    return r;
}
__device__ __forceinline__ float ex2f(float x) {
    float y;
    asm("ex2.approx.f32 %0, %1;" : "=f"(y) : "f"(x));
    return y;
}
__device__ __forceinline__ void cp16(uint32_t dst, const void* src) {
    asm volatile("cp.async.cg.shared.global [%0], [%1], 16;"
                 :: "r"(dst), "l"(__cvta_generic_to_global(src)) : "memory");
}
#define CP_COMMIT() asm volatile("cp.async.commit_group;" ::: "memory")
#define CP_WAIT0()  asm volatile("cp.async.wait_group 0;" ::: "memory")

// ============================================================================
// Kernel 0: weights fp32 -> fp16, stacked [Wk;Wq;Wv] = [192][512], 4/thread
// ============================================================================
__global__ __launch_bounds__(128) void w16_kernel(
    const float* __restrict__ Wk, const float* __restrict__ Wq,
    const float* __restrict__ Wv)
{
    int i4 = (blockIdx.x * 128 + threadIdx.x) * 4;   // 0..98300
    const float* src;
    int off;
    if (i4 < 64 * EMBED)       { src = Wk; off = i4; }
    else if (i4 < 128 * EMBED) { src = Wq; off = i4 - 64 * EMBED; }
    else                       { src = Wv; off = i4 - 128 * EMBED; }
    float4 f = *(const float4*)&src[off];
    *(uint2*)&gW16[i4] = make_uint2(cvt2h(f.x, f.y), cvt2h(f.z, f.w));
}

// ============================================================================
// Kernel 1: KQV projection via fp16 mma.sync (W via cp.async, x converted
// inline). PDL: x chunk-0 staged before griddepsync. Double-buffered.
// ============================================================================
#define PX(s) ((s) * 8192)             // 2 x 8KB x buffers
#define PW(s) (16384 + (s) * 24576)    // 2 x 24KB W buffers
#define PSMEM 65536

__global__ __launch_bounds__(256) void proj_mma(const float* __restrict__ x)
{
    extern __shared__ __align__(16) uint8_t smem[];
    const uint32_t sb = smem_u32(smem);

    const int tid  = threadIdx.x;
    const int wid  = tid >> 5;
    const int lane = tid & 31;
    const int wm   = (wid & 3) * 16;    // warp row base
    const int h    = wid >> 2;          // warp n-half (0: cols 0-95, 1: 96-191)
    const int g    = lane >> 2;
    const int tg   = lane & 3;
    const int mblk = blockIdx.x * 64;

    float c[12][4];
#pragma unroll
    for (int j = 0; j < 12; j++)
#pragma unroll
        for (int q = 0; q < 4; q++) c[j][q] = 0.f;

#define STAGE_W(kc, s)                                                              \
    do {                                                                            \
        _Pragma("unroll")                                                           \
        for (int it = 0; it < 6; it++) {                                            \
            int idx = tid + it * 256;          /* 0..1535 uint4s */                 \
            int r = idx >> 3, u = idx & 7;                                          \
            uint32_t dst = r * 128 + ((u * 16) ^ ((r & 7) << 4));                   \
            cp16(sb + PW(s) + dst, &gW16[(size_t)r * EMBED + (kc) * 64 + u * 8]);   \
        }                                                                           \
    } while (0)

#define STAGE_X(kc, s)                                                              \
    do {                                                                            \
        _Pragma("unroll")                                                           \
        for (int it = 0; it < 4; it++) {                                            \
            int idx = tid + it * 256;          /* 0..1023 float4s */                \
            int r = idx >> 4, c4 = idx & 15;                                        \
            float4 f = *(const float4*)&x[(size_t)(mblk + r) * EMBED + (kc) * 64 + c4 * 4]; \
            uint32_t dst = r * 128 + ((c4 * 8) ^ ((r & 7) << 4));                   \
            *(uint2*)(smem + PX(s) + dst) =                                         \
                make_uint2(cvt2h(f.x, f.y), cvt2h(f.z, f.w));                       \
        }                                                                           \
    } while (0)

    // x chunk 0 is independent of w16's output -> stage it before the PDL sync
    STAGE_X(0, 0);
    cudaGridDependencySynchronize();   // gW16 now valid
    STAGE_W(0, 0);
    CP_COMMIT();
    CP_WAIT0();
    __syncthreads();

    for (int kc = 0; kc < 8; kc++) {
        const int s = kc & 1;
        if (kc < 7) {
            STAGE_W(kc + 1, s ^ 1);
            CP_COMMIT();
            STAGE_X(kc + 1, s ^ 1);
        }

#pragma unroll
        for (int ks = 0; ks < 4; ks++) {
            uint32_t ah[4];
            int arow = wm + (lane & 15);
            uint32_t abyte = (uint32_t)((ks * 32 + (lane >> 4) * 16) ^ ((arow & 7) << 4));
            ldsm4(ah, sb + PX(s) + arow * 128 + abyte);
#pragma unroll
            for (int jj = 0; jj < 6; jj++) {
                uint32_t b[4];
                int brow = h * 96 + jj * 16 + (lane & 7) + ((lane >> 4) << 3);
                uint32_t bby = (uint32_t)((ks * 32 + ((lane >> 3) & 1) * 16) ^ ((brow & 7) << 4));
                ldsm4(b, sb + PW(s) + brow * 128 + bby);
                mma16816(c[2 * jj],     ah, b[0], b[1]);
                mma16816(c[2 * jj + 1], ah, b[2], b[3]);
            }
        }
        if (kc < 7) CP_WAIT0();
        __syncthreads();
    }
#undef STAGE_W
#undef STAGE_X

    const int m0 = mblk + wm + g;
#pragma unroll
    for (int j = 0; j < 12; j++) {
        int col = h * 96 + j * 8 + 2 * tg;
        if (col < 64) {
            *(uint32_t*)&gK16[(size_t)m0 * HEAD + col]       = cvt2h(c[j][0], c[j][1]);
            *(uint32_t*)&gK16[(size_t)(m0 + 8) * HEAD + col] = cvt2h(c[j][2], c[j][3]);
        } else if (col < 128) {
            int hh = col - 64;
            *(uint32_t*)&gQ16[(size_t)m0 * HEAD + hh]       = cvt2h(c[j][0] * QSC2, c[j][1] * QSC2);
            *(uint32_t*)&gQ16[(size_t)(m0 + 8) * HEAD + hh] = cvt2h(c[j][2] * QSC2, c[j][3] * QSC2);
        } else {
            int hh = col - 128;
            *(uint32_t*)&gV16[(size_t)m0 * HEAD + hh]       = cvt2h(c[j][0], c[j][1]);
            *(uint32_t*)&gV16[(size_t)(m0 + 8) * HEAD + hh] = cvt2h(c[j][2], c[j][3]);
        }
    }
}

// ============================================================================
// Kernel 2a: attention pass 1 (split-K), register-resident P, l via MMA,
// SOFTWARE-PIPELINED: MMA2(t-1) issued between MMA1(t) and exp(t), so the
// tensor pipe drains queued MMAs during the exp phase. V is 3-staged
// (stage t-1 still live at iter t while t+1 prefetches); K 2-staged.
// ============================================================================
#define AQS  0            // 8KB  Q
#define AK0  8192         // 2x8KB K
#define AV0  24576        // 3x8KB V
#define ASMEM 49152

__global__ __launch_bounds__(128, 4) void attn_part(float* __restrict__ out)
{
    __shared__ __align__(16) uint8_t smem[ASMEM];
    const uint32_t sb = smem_u32(smem);

    // big-qt units first
    const int slot = (NUNITS - 1) - blockIdx.x;
    const int b = slot / 160;
    const int r = slot % 160;
    int qt, ch;
    if (r < 16)      { qt = r;                    ch = 0; }
    else if (r < 48) { qt = 16 + ((r - 16) >> 1); ch = (r - 16) & 1; }
    else if (r < 96) { qt = 32 + (r - 48) / 3;    ch = (r - 48) % 3; }
    else             { qt = 48 + ((r - 96) >> 2); ch = (r - 96) & 3; }
    const int kt0 = ch * 16;
    const int kt1 = (kt0 + 16 < qt + 1) ? (kt0 + 16) : (qt + 1);
    const int nit = kt1 - kt0;
    const bool single = (r < 16);

    const int tid  = threadIdx.x;
    const int wid  = tid >> 5;
    const int lane = tid & 31;
    const int m0w  = wid * 16;
    const int g    = lane >> 2;
    const int tg   = lane & 3;

    const __half* __restrict__ Qg = gQ16 + (size_t)(b * SEQ + qt * 64) * HEAD;
    const __half* __restrict__ Kb = gK16 + (size_t)(b * SEQ) * HEAD;
    const __half* __restrict__ Vb = gV16 + (size_t)(b * SEQ) * HEAD;

    cudaGridDependencySynchronize();   // gQ16/gK16/gV16 now valid

    // stage Q + first K/V tile
#pragma unroll
    for (int it = 0; it < 4; it++) {
        int idx = tid + it * 128;          // 0..511
        int rr = idx >> 3, u = idx & 7;
        uint32_t dst = rr * 128 + ((u * 16) ^ ((rr & 7) << 4));
        cp16(sb + AQS + dst, &Qg[rr * HEAD + u * 8]);
        cp16(sb + AK0 + dst, &Kb[(size_t)(kt0 * 64 + rr) * HEAD + u * 8]);
        cp16(sb + AV0 + dst, &Vb[(size_t)(kt0 * 64 + rr) * HEAD + u * 8]);
    }
    CP_COMMIT();
    CP_WAIT0();
    __syncthreads();

    uint32_t qa[4][4];
    {
        int arow = m0w + (lane & 15);
#pragma unroll
        for (int k4 = 0; k4 < 4; k4++) {
            uint32_t abyte = (uint32_t)((k4 * 32 + (lane >> 4) * 16) ^ ((arow & 7) << 4));
            ldsm4(qa[k4], sb + AQS + arow * 128 + abyte);
        }
    }

    float oc[8][4];
#pragma unroll
    for (int j = 0; j < 8; j++)
#pragma unroll
        for (int q = 0; q < 4; q++) oc[j][q] = 0.f;
    float lc[4] = {0.f, 0.f, 0.f, 0.f};   // l accumulator (MMA C-frag)
    uint32_t pfr[4][4];                    // P frags carried across iterations

    // MMA2 for one deferred iteration (V stage vs)
    #define DO_MMA2(vs)                                                             \
    do {                                                                            \
        const uint32_t vbase = sb + AV0 + (vs) * 8192;                              \
        _Pragma("unroll")                                                           \
        for (int jj = 0; jj < 4; jj++) {                                            \
            _Pragma("unroll")                                                       \
            for (int k4 = 0; k4 < 4; k4++) {                                        \
                int krow = k4 * 16 + (lane & 7) + (((lane >> 3) & 1) << 3);         \
                uint32_t vby = (uint32_t)(((jj * 16 + ((lane >> 4) << 3)) * 2) ^ ((krow & 7) << 4)); \
                uint32_t bv[4];                                                     \
                ldsm4t(bv, vbase + krow * 128 + vby);                               \
                mma16816(oc[2 * jj],     pfr[k4], bv[0], bv[1]);                    \
                mma16816(oc[2 * jj + 1], pfr[k4], bv[2], bv[3]);                    \
            }                                                                       \
        }                                                                           \
    } while (0)

    int vprev = 0;   // V stage of the deferred (previous) iteration
    for (int i = 0; i < nit; i++) {
        const int kt = kt0 + i;
        // prefetch tile i+1 (K stage (i+1)&1, V stage (i+1)%3)
        if (i + 1 < nit) {
            uint32_t kbuf = AK0 + ((i + 1) & 1) * 8192;
            uint32_t vbuf = AV0 + ((i + 1) % 3) * 8192;
            const __half* Kg = Kb + (size_t)(kt + 1) * 64 * HEAD;
            const __half* Vg = Vb + (size_t)(kt + 1) * 64 * HEAD;
#pragma unroll
            for (int it = 0; it < 4; it++) {
                int idx = tid + it * 128;
                int rr = idx >> 3, u = idx & 7;
                uint32_t dst = rr * 128 + ((u * 16) ^ ((rr & 7) << 4));
                cp16(sb + kbuf + dst, &Kg[rr * HEAD + u * 8]);
                cp16(sb + vbuf + dst, &Vg[rr * HEAD + u * 8]);
            }
            CP_COMMIT();
        }

        const uint32_t kbase = sb + AK0 + (i & 1) * 8192;

        // ---- MMA1: S = Q @ K^T ----
        float sc[8][4];
#pragma unroll
        for (int j = 0; j < 8; j++)
#pragma unroll
            for (int q = 0; q < 4; q++) sc[j][q] = 0.f;
#pragma unroll
        for (int jj = 0; jj < 4; jj++) {
            int brow = jj * 16 + (lane & 7) + ((lane >> 4) << 3);
#pragma unroll
            for (int k4 = 0; k4 < 4; k4++) {
                uint32_t bby = (uint32_t)((k4 * 32 + ((lane >> 3) & 1) * 16) ^ ((brow & 7) << 4));
                uint32_t bk[4];
                ldsm4(bk, kbase + brow * 128 + bby);
                mma16816(sc[2 * jj],     qa[k4], bk[0], bk[1]);
                mma16816(sc[2 * jj + 1], qa[k4], bk[2], bk[3]);
            }
        }

        // ---- deferred MMA2 for iteration i-1 (keeps tensor pipe fed during exp) ----
        if (i > 0) DO_MMA2(vprev);

        // ---- causal mask (diag tile only): -inf -> exp gives 0 ----
        if (kt == qt) {
            const int lr0 = m0w + g, lr1 = lr0 + 8;
#pragma unroll
            for (int jn = 0; jn < 8; jn++) {
                int c0 = jn * 8 + 2 * tg;
                if (c0     > lr0) sc[jn][0] = NEG_INF;
                if (c0 + 1 > lr0) sc[jn][1] = NEG_INF;
                if (c0     > lr1) sc[jn][2] = NEG_INF;
                if (c0 + 1 > lr1) sc[jn][3] = NEG_INF;
            }
        }

        // ---- exp2 + pack into MMA2 A-frags (register-resident P) ----
#pragma unroll
        for (int k4 = 0; k4 < 4; k4++) {
            pfr[k4][0] = cvt2h(ex2f(sc[2 * k4][0]),     ex2f(sc[2 * k4][1]));
            pfr[k4][1] = cvt2h(ex2f(sc[2 * k4][2]),     ex2f(sc[2 * k4][3]));
            pfr[k4][2] = cvt2h(ex2f(sc[2 * k4 + 1][0]), ex2f(sc[2 * k4 + 1][1]));
            pfr[k4][3] = cvt2h(ex2f(sc[2 * k4 + 1][2]), ex2f(sc[2 * k4 + 1][3]));
            mma16816(lc, pfr[k4], ONES16, ONES16);   // l row-sums via MMA
        }
        vprev = i % 3;

        if (i + 1 < nit) {
            CP_WAIT0();
            __syncthreads();
        }
    }
    // final deferred MMA2
    DO_MMA2(vprev);
    #undef DO_MMA2

    const float ls0 = lc[0];
    const float ls1 = lc[2];
    const int lr0 = m0w + g, lr1 = lr0 + 8;

    if (single) {
        const float inv0 = 1.0f / ls0;
        const float inv1 = 1.0f / ls1;
        const size_t ro = (size_t)(b * SEQ + qt * 64 + lr0) * HEAD;
#pragma unroll
        for (int jn = 0; jn < 8; jn++) {
            int col = jn * 8 + 2 * tg;
            *(float2*)&out[ro + col]            = make_float2(oc[jn][0] * inv0, oc[jn][1] * inv0);
            *(float2*)&out[ro + 8 * HEAD + col] = make_float2(oc[jn][2] * inv1, oc[jn][3] * inv1);
        }
    } else {
        __half* Op = gOp16 + (size_t)slot * 4096;
#pragma unroll
        for (int jn = 0; jn < 8; jn++) {
            int col = jn * 8 + 2 * tg;
            *(uint32_t*)&Op[lr0 * 64 + col] = cvt2h(oc[jn][0], oc[jn][1]);
            *(uint32_t*)&Op[lr1 * 64 + col] = cvt2h(oc[jn][2], oc[jn][3]);
        }
        if (tg == 0) {
            gLp[slot * 64 + lr0] = ls0;
            gLp[slot * 64 + lr1] = ls1;
        }
    }
}

// ============================================================================
// Kernel 2b: combine partials + normalize, qt >= 16 only.
// 768 CTAs (= 4 b x 48 qt x 4 row-quarters) x 128 threads;
// thread = (row, 8-col strip).
// ============================================================================
__global__ __launch_bounds__(128) void attn_comb(float* __restrict__ out)
{
    const int bid = blockIdx.x;          // 0..767
    const int u   = bid >> 2;
    const int rq  = bid & 3;             // row quarter
    const int b   = u / 48;
    const int qt  = 16 + (u % 48);
    const int tid = threadIdx.x;
    const int row = rq * 16 + (tid >> 3);   // 0..63
    const int col = (tid & 7) * 8;          // 0..56 step 8

    const int nch = (qt >> 4) + 1;       // 2..4
    int off0;
    if (qt < 32)      off0 = 16 + (qt - 16) * 2;
    else if (qt < 48) off0 = 48 + (qt - 32) * 3;
    else              off0 = 96 + (qt - 48) * 4;
    const int slot0 = b * 160 + off0;

    cudaGridDependencySynchronize();   // gOp16/gLp now valid

    float acc[8];
#pragma unroll
    for (int i = 0; i < 8; i++) acc[i] = 0.f;
    float lsum = 0.f;

#pragma unroll 4
    for (int c = 0; c < nch; c++) {
        const __half* Op = gOp16 + (size_t)(slot0 + c) * 4096 + row * 64 + col;
        uint4 v = *(const uint4*)Op;         // 8 halves
        lsum += gLp[(slot0 + c) * 64 + row];
        const uint32_t* w = &v.x;
#pragma unroll
        for (int q = 0; q < 4; q++) {
            float2 f = __half22float2(*(const __half2*)&w[q]);
            acc[2 * q]     += f.x;
            acc[2 * q + 1] += f.y;
        }
    }

    const float inv = 1.0f / lsum;
    float* dst = out + ((size_t)(b * SEQ + qt * 64 + row)) * HEAD + col;
    *(float4*)&dst[0] = make_float4(acc[0] * inv, acc[1] * inv, acc[2] * inv, acc[3] * inv);
    *(float4*)&dst[4] = make_float4(acc[4] * inv, acc[5] * inv, acc[6] * inv, acc[7] * inv);
}

// ============================================================================
// launch (PDL-chained)
// ============================================================================
static inline void launch_pdl(const void* fn, dim3 grid, dim3 block, size_t smem,
                              void** args)
{
    cudaLaunchConfig_t cfg = {};
    cfg.gridDim = grid;
    cfg.blockDim = block;
    cfg.dynamicSmemBytes = smem;
    cudaLaunchAttribute attr[1];
    attr[0].id = cudaLaunchAttributeProgrammaticStreamSerialization;
    attr[0].val.programmaticStreamSerializationAllowed = 1;
    cfg.attrs = attr;
    cfg.numAttrs = 1;
    cudaLaunchKernelExC(&cfg, fn, args);
}

extern "C" void kernel_launch(void* const* d_in, const int* in_sizes, int n_in,
                              void* d_out, int out_size)
{
    const float* x  = (const float*)d_in[0];
    const float* Wk = (const float*)d_in[1];
    const float* Wq = (const float*)d_in[2];
    const float* Wv = (const float*)d_in[3];
    float* out = (float*)d_out;

    w16_kernel<<<192, 128>>>(Wk, Wq, Wv);

    static int smem_set = 0;
    if (!smem_set) {
        cudaFuncSetAttribute(proj_mma, cudaFuncAttributeMaxDynamicSharedMemorySize, PSMEM);
        smem_set = 1;
    }

    {
        void* args[] = { (void*)&x };
        launch_pdl((const void*)proj_mma, dim3(NTOK / 64), dim3(256), PSMEM, args);
    }
    {
        void* args[] = { (void*)&out };
        launch_pdl((const void*)attn_part, dim3(NUNITS), dim3(128), 0, args);
    }
    {
        void* args[] = { (void*)&out };
        launch_pdl((const void*)attn_comb, dim3(768), dim3(128), 0, args);
    }
}

// round 14
// speedup vs baseline: 1.0359x; 1.0359x over previous
#include <cuda_runtime.h>
#include <cuda_fp16.h>
#include <cstdint>

#define BATCH 4
#define SEQ   4096
#define EMBED 512
#define HEAD  64
#define NTOK  (BATCH * SEQ)
// C^-0.5 * log2(e): Q pre-scale so softmax uses raw ex2
#define QSC2  (0.04419417382415922f * 1.4426950408889634f)

#define NUNITS 576          // split-K work units (144 per batch), 128-row q-tiles
#define NEG_INF __int_as_float(0xff800000)
#define ONES16  0x3C003C00u // (1.0h, 1.0h)

// ---------------- scratch (device globals) ----------------
__device__ __half gK16[NTOK * HEAD];   // [t][h]
__device__ __half gQ16[NTOK * HEAD];   // [t][h], pre-scaled by QSC2
__device__ __half gV16[NTOK * HEAD];   // [t][h]
__device__ __half gW16[192 * EMBED];   // [Wk;Wq;Wv] rows, fp16
__device__ __half gOp16[NUNITS * 128 * 64]; // partial O (unnormalized, fp16)
__device__ float  gLp[NUNITS * 128];        // partial l (fp32)

// ---------------- helpers ----------------
__device__ __forceinline__ uint32_t smem_u32(const void* p) {
    uint32_t a;
    asm("{ .reg .u64 t; cvta.to.shared.u64 t, %1; cvt.u32.u64 %0, t; }" : "=r"(a) : "l"(p));
    return a;
}
__device__ __forceinline__ void ldsm4(uint32_t* r, uint32_t addr) {
    asm volatile("ldmatrix.sync.aligned.m8n8.x4.shared.b16 {%0,%1,%2,%3}, [%4];"
                 : "=r"(r[0]), "=r"(r[1]), "=r"(r[2]), "=r"(r[3]) : "r"(addr));
}
__device__ __forceinline__ void ldsm4t(uint32_t* r, uint32_t addr) {
    asm volatile("ldmatrix.sync.aligned.m8n8.x4.trans.shared.b16 {%0,%1,%2,%3}, [%4];"
                 : "=r"(r[0]), "=r"(r[1]), "=r"(r[2]), "=r"(r[3]) : "r"(addr));
}
__device__ __forceinline__ void mma16816(float* c, const uint32_t* a, uint32_t b0, uint32_t b1) {
    asm volatile(
        "mma.sync.aligned.m16n8k16.row.col.f32.f16.f16.f32 "
        "{%0,%1,%2,%3}, {%4,%5,%6,%7}, {%8,%9}, {%0,%1,%2,%3};"
        : "+f"(c[0]), "+f"(c[1]), "+f"(c[2]), "+f"(c[3])
        : "r"(a[0]), "r"(a[1]), "r"(a[2]), "r"(a[3]), "r"(b0), "r"(b1));
}
// single-instruction fp32x2 -> half2 pack (low = a, high = b)
__device__ __forceinline__ uint32_t cvt2h(float a, float b) {
    uint32_t r;
    asm("cvt.rn.f16x2.f32 %0, %1, %2;" : "=r"(r) : "f"(b), "f"(a));
    return r;
}
__device__ __forceinline__ float ex2f(float x) {
    float y;
    asm("ex2.approx.f32 %0, %1;" : "=f"(y) : "f"(x));
    return y;
}
__device__ __forceinline__ void cp16(uint32_t dst, const void* src) {
    asm volatile("cp.async.cg.shared.global [%0], [%1], 16;"
                 :: "r"(dst), "l"(__cvta_generic_to_global(src)) : "memory");
}
#define CP_COMMIT() asm volatile("cp.async.commit_group;" ::: "memory")
#define CP_WAIT0()  asm volatile("cp.async.wait_group 0;" ::: "memory")

// ============================================================================
// Kernel 0: weights fp32 -> fp16, stacked [Wk;Wq;Wv] = [192][512], 4/thread
// ============================================================================
__global__ __launch_bounds__(128) void w16_kernel(
    const float* __restrict__ Wk, const float* __restrict__ Wq,
    const float* __restrict__ Wv)
{
    int i4 = (blockIdx.x * 128 + threadIdx.x) * 4;   // 0..98300
    const float* src;
    int off;
    if (i4 < 64 * EMBED)       { src = Wk; off = i4; }
    else if (i4 < 128 * EMBED) { src = Wq; off = i4 - 64 * EMBED; }
    else                       { src = Wv; off = i4 - 128 * EMBED; }
    float4 f = *(const float4*)&src[off];
    *(uint2*)&gW16[i4] = make_uint2(cvt2h(f.x, f.y), cvt2h(f.z, f.w));
}

// ============================================================================
// Kernel 1: KQV projection via fp16 mma.sync (W via cp.async, x converted
// inline). PDL: x chunk-0 staged before griddepsync. Double-buffered.
// ============================================================================
#define PX(s) ((s) * 8192)             // 2 x 8KB x buffers
#define PW(s) (16384 + (s) * 24576)    // 2 x 24KB W buffers
#define PSMEM 65536

__global__ __launch_bounds__(256) void proj_mma(const float* __restrict__ x)
{
    extern __shared__ __align__(16) uint8_t smem[];
    const uint32_t sb = smem_u32(smem);

    const int tid  = threadIdx.x;
    const int wid  = tid >> 5;
    const int lane = tid & 31;
    const int wm   = (wid & 3) * 16;    // warp row base
    const int h    = wid >> 2;          // warp n-half (0: cols 0-95, 1: 96-191)
    const int g    = lane >> 2;
    const int tg   = lane & 3;
    const int mblk = blockIdx.x * 64;

    float c[12][4];
#pragma unroll
    for (int j = 0; j < 12; j++)
#pragma unroll
        for (int q = 0; q < 4; q++) c[j][q] = 0.f;

#define STAGE_W(kc, s)                                                              \
    do {                                                                            \
        _Pragma("unroll")                                                           \
        for (int it = 0; it < 6; it++) {                                            \
            int idx = tid + it * 256;          /* 0..1535 uint4s */                 \
            int r = idx >> 3, u = idx & 7;                                          \
            uint32_t dst = r * 128 + ((u * 16) ^ ((r & 7) << 4));                   \
            cp16(sb + PW(s) + dst, &gW16[(size_t)r * EMBED + (kc) * 64 + u * 8]);   \
        }                                                                           \
    } while (0)

#define STAGE_X(kc, s)                                                              \
    do {                                                                            \
        _Pragma("unroll")                                                           \
        for (int it = 0; it < 4; it++) {                                            \
            int idx = tid + it * 256;          /* 0..1023 float4s */                \
            int r = idx >> 4, c4 = idx & 15;                                        \
            float4 f = *(const float4*)&x[(size_t)(mblk + r) * EMBED + (kc) * 64 + c4 * 4]; \
            uint32_t dst = r * 128 + ((c4 * 8) ^ ((r & 7) << 4));                   \
            *(uint2*)(smem + PX(s) + dst) =                                         \
                make_uint2(cvt2h(f.x, f.y), cvt2h(f.z, f.w));                       \
        }                                                                           \
    } while (0)

    // x chunk 0 is independent of w16's output -> stage it before the PDL sync
    STAGE_X(0, 0);
    cudaGridDependencySynchronize();   // gW16 now valid
    STAGE_W(0, 0);
    CP_COMMIT();
    CP_WAIT0();
    __syncthreads();

    for (int kc = 0; kc < 8; kc++) {
        const int s = kc & 1;
        if (kc < 7) {
            STAGE_W(kc + 1, s ^ 1);
            CP_COMMIT();
            STAGE_X(kc + 1, s ^ 1);
        }

#pragma unroll
        for (int ks = 0; ks < 4; ks++) {
            uint32_t ah[4];
            int arow = wm + (lane & 15);
            uint32_t abyte = (uint32_t)((ks * 32 + (lane >> 4) * 16) ^ ((arow & 7) << 4));
            ldsm4(ah, sb + PX(s) + arow * 128 + abyte);
#pragma unroll
            for (int jj = 0; jj < 6; jj++) {
                uint32_t b[4];
                int brow = h * 96 + jj * 16 + (lane & 7) + ((lane >> 4) << 3);
                uint32_t bby = (uint32_t)((ks * 32 + ((lane >> 3) & 1) * 16) ^ ((brow & 7) << 4));
                ldsm4(b, sb + PW(s) + brow * 128 + bby);
                mma16816(c[2 * jj],     ah, b[0], b[1]);
                mma16816(c[2 * jj + 1], ah, b[2], b[3]);
            }
        }
        if (kc < 7) CP_WAIT0();
        __syncthreads();
    }
#undef STAGE_W
#undef STAGE_X

    const int m0 = mblk + wm + g;
#pragma unroll
    for (int j = 0; j < 12; j++) {
        int col = h * 96 + j * 8 + 2 * tg;
        if (col < 64) {
            *(uint32_t*)&gK16[(size_t)m0 * HEAD + col]       = cvt2h(c[j][0], c[j][1]);
            *(uint32_t*)&gK16[(size_t)(m0 + 8) * HEAD + col] = cvt2h(c[j][2], c[j][3]);
        } else if (col < 128) {
            int hh = col - 64;
            *(uint32_t*)&gQ16[(size_t)m0 * HEAD + hh]       = cvt2h(c[j][0] * QSC2, c[j][1] * QSC2);
            *(uint32_t*)&gQ16[(size_t)(m0 + 8) * HEAD + hh] = cvt2h(c[j][2] * QSC2, c[j][3] * QSC2);
        } else {
            int hh = col - 128;
            *(uint32_t*)&gV16[(size_t)m0 * HEAD + hh]       = cvt2h(c[j][0], c[j][1]);
            *(uint32_t*)&gV16[(size_t)(m0 + 8) * HEAD + hh] = cvt2h(c[j][2], c[j][3]);
        }
    }
}

// ============================================================================
// Kernel 2a: attention pass 1 (split-K), 128-row q-tiles, warp = 32 rows
// (2 row-groups) so each ldsm'd K/V B-frag feeds 2x the MMA work (smem
// crossbar traffic halves per unit work). Register-resident P; l via MMA.
// Unit = (b, 128-row q-tile, <=8 key tiles). nch(q) = (q>>2)+1;
// off0(q) = (k+1)*(q-2k), k = q>>2. q<4: single chunk -> direct write.
// ============================================================================
#define AQS  0            // 16KB Q (128 rows)
#define AK0  16384        // 2x8KB K
#define AV0  32768        // 2x8KB V
#define ASMEM 49152

__global__ __launch_bounds__(128) void attn_part(float* __restrict__ out)
{
    __shared__ __align__(16) uint8_t smem[ASMEM];
    const uint32_t sb = smem_u32(smem);

    // big-q units first
    const int slot = (NUNITS - 1) - blockIdx.x;
    const int b = slot / 144;
    const int r = slot % 144;
    int k = 0;
    while (r >= 2 * (k + 1) * (k + 2)) k++;      // block index, nch = k+1
    const int rr2 = r - 2 * k * (k + 1);
    const int q   = 4 * k + rr2 / (k + 1);
    const int ch  = rr2 % (k + 1);
    const int kt0 = ch * 8;
    const int ktop = 2 * q + 2;                   // total key tiles for this q
    const int kt1 = (kt0 + 8 < ktop) ? (kt0 + 8) : ktop;
    const int nit = kt1 - kt0;
    const bool single = (k == 0);

    const int tid  = threadIdx.x;
    const int wid  = tid >> 5;
    const int lane = tid & 31;
    const int m0w  = wid * 32;           // warp's 32-row base
    const int g    = lane >> 2;
    const int tg   = lane & 3;

    const __half* __restrict__ Qg = gQ16 + (size_t)(b * SEQ + q * 128) * HEAD;
    const __half* __restrict__ Kb = gK16 + (size_t)(b * SEQ) * HEAD;
    const __half* __restrict__ Vb = gV16 + (size_t)(b * SEQ) * HEAD;

    cudaGridDependencySynchronize();   // gQ16/gK16/gV16 now valid

    // stage Q (128 rows = 1024 uint4) + first K/V tile (512 uint4 each)
#pragma unroll
    for (int it = 0; it < 8; it++) {
        int idx = tid + it * 128;          // 0..1023
        int rw = idx >> 3, u = idx & 7;
        uint32_t dst = rw * 128 + ((u * 16) ^ ((rw & 7) << 4));
        cp16(sb + AQS + dst, &Qg[rw * HEAD + u * 8]);
    }
#pragma unroll
    for (int it = 0; it < 4; it++) {
        int idx = tid + it * 128;          // 0..511
        int rw = idx >> 3, u = idx & 7;
        uint32_t dst = rw * 128 + ((u * 16) ^ ((rw & 7) << 4));
        cp16(sb + AK0 + dst, &Kb[(size_t)(kt0 * 64 + rw) * HEAD + u * 8]);
        cp16(sb + AV0 + dst, &Vb[(size_t)(kt0 * 64 + rw) * HEAD + u * 8]);
    }
    CP_COMMIT();
    CP_WAIT0();
    __syncthreads();

    // Q A-frags for both row-groups, loaded once
    uint32_t qa[2][4][4];
#pragma unroll
    for (int rg = 0; rg < 2; rg++) {
        int arow = m0w + rg * 16 + (lane & 15);
#pragma unroll
        for (int k4 = 0; k4 < 4; k4++) {
            uint32_t abyte = (uint32_t)((k4 * 32 + (lane >> 4) * 16) ^ ((arow & 7) << 4));
            ldsm4(qa[rg][k4], sb + AQS + arow * 128 + abyte);
        }
    }

    float oc[2][8][4];
#pragma unroll
    for (int rg = 0; rg < 2; rg++)
#pragma unroll
        for (int j = 0; j < 8; j++)
#pragma unroll
            for (int qq = 0; qq < 4; qq++) oc[rg][j][qq] = 0.f;
    float lc[2][4] = {{0.f,0.f,0.f,0.f},{0.f,0.f,0.f,0.f}};

    int stage = 0;
    for (int i = 0; i < nit; i++) {
        const int kt = kt0 + i;
        if (i + 1 < nit) {
            uint32_t kbuf = AK0 + ((i + 1) & 1) * 8192;
            uint32_t vbuf = AV0 + ((i + 1) & 1) * 8192;
            const __half* Kg = Kb + (size_t)(kt + 1) * 64 * HEAD;
            const __half* Vg = Vb + (size_t)(kt + 1) * 64 * HEAD;
#pragma unroll
            for (int it = 0; it < 4; it++) {
                int idx = tid + it * 128;
                int rw = idx >> 3, u = idx & 7;
                uint32_t dst = rw * 128 + ((u * 16) ^ ((rw & 7) << 4));
                cp16(sb + kbuf + dst, &Kg[rw * HEAD + u * 8]);
                cp16(sb + vbuf + dst, &Vg[rw * HEAD + u * 8]);
            }
            CP_COMMIT();
        }

        const uint32_t kbase = sb + AK0 + stage * 8192;
        const uint32_t vbase = sb + AV0 + stage * 8192;

        // ---- MMA1: S = Q @ K^T (both row-groups share each B-frag) ----
        float sc[2][8][4];
#pragma unroll
        for (int rg = 0; rg < 2; rg++)
#pragma unroll
            for (int j = 0; j < 8; j++)
#pragma unroll
                for (int qq = 0; qq < 4; qq++) sc[rg][j][qq] = 0.f;
#pragma unroll
        for (int jj = 0; jj < 4; jj++) {
            int brow = jj * 16 + (lane & 7) + ((lane >> 4) << 3);
#pragma unroll
            for (int k4 = 0; k4 < 4; k4++) {
                uint32_t bby = (uint32_t)((k4 * 32 + ((lane >> 3) & 1) * 16) ^ ((brow & 7) << 4));
                uint32_t bk[4];
                ldsm4(bk, kbase + brow * 128 + bby);
#pragma unroll
                for (int rg = 0; rg < 2; rg++) {
                    mma16816(sc[rg][2 * jj],     qa[rg][k4], bk[0], bk[1]);
                    mma16816(sc[rg][2 * jj + 1], qa[rg][k4], bk[2], bk[3]);
                }
            }
        }

        // ---- causal mask on overlapping tiles (global indices) ----
        if (kt >= 2 * q) {
            const int kb = kt * 64;
            const int qb = q * 128;
#pragma unroll
            for (int rg = 0; rg < 2; rg++) {
                const int qr0 = qb + m0w + rg * 16 + g;
                const int qr1 = qr0 + 8;
#pragma unroll
                for (int jn = 0; jn < 8; jn++) {
                    int kc = kb + jn * 8 + 2 * tg;
                    if (kc     > qr0) sc[rg][jn][0] = NEG_INF;
                    if (kc + 1 > qr0) sc[rg][jn][1] = NEG_INF;
                    if (kc     > qr1) sc[rg][jn][2] = NEG_INF;
                    if (kc + 1 > qr1) sc[rg][jn][3] = NEG_INF;
                }
            }
        }

        // ---- exp2 + pack into MMA2 A-frags; l via MMA ----
        uint32_t pfr[2][4][4];
#pragma unroll
        for (int rg = 0; rg < 2; rg++)
#pragma unroll
            for (int k4 = 0; k4 < 4; k4++) {
                pfr[rg][k4][0] = cvt2h(ex2f(sc[rg][2 * k4][0]),     ex2f(sc[rg][2 * k4][1]));
                pfr[rg][k4][1] = cvt2h(ex2f(sc[rg][2 * k4][2]),     ex2f(sc[rg][2 * k4][3]));
                pfr[rg][k4][2] = cvt2h(ex2f(sc[rg][2 * k4 + 1][0]), ex2f(sc[rg][2 * k4 + 1][1]));
                pfr[rg][k4][3] = cvt2h(ex2f(sc[rg][2 * k4 + 1][2]), ex2f(sc[rg][2 * k4 + 1][3]));
                mma16816(lc[rg], pfr[rg][k4], ONES16, ONES16);
            }

        // ---- MMA2: O += P @ V (both row-groups share each B-frag) ----
#pragma unroll
        for (int jj = 0; jj < 4; jj++) {
#pragma unroll
            for (int k4 = 0; k4 < 4; k4++) {
                int krow = k4 * 16 + (lane & 7) + (((lane >> 3) & 1) << 3);
                uint32_t vby = (uint32_t)(((jj * 16 + ((lane >> 4) << 3)) * 2) ^ ((krow & 7) << 4));
                uint32_t bv[4];
                ldsm4t(bv, vbase + krow * 128 + vby);
#pragma unroll
                for (int rg = 0; rg < 2; rg++) {
                    mma16816(oc[rg][2 * jj],     pfr[rg][k4], bv[0], bv[1]);
                    mma16816(oc[rg][2 * jj + 1], pfr[rg][k4], bv[2], bv[3]);
                }
            }
        }

        if (i + 1 < nit) {
            CP_WAIT0();
            __syncthreads();
        }
        stage ^= 1;
    }

    if (single) {
#pragma unroll
        for (int rg = 0; rg < 2; rg++) {
            const float inv0 = 1.0f / lc[rg][0];
            const float inv1 = 1.0f / lc[rg][2];
            const int row0 = m0w + rg * 16 + g;
            const size_t ro = (size_t)(b * SEQ + q * 128 + row0) * HEAD;
#pragma unroll
            for (int jn = 0; jn < 8; jn++) {
                int col = jn * 8 + 2 * tg;
                *(float2*)&out[ro + col] =
                    make_float2(oc[rg][jn][0] * inv0, oc[rg][jn][1] * inv0);
                *(float2*)&out[ro + 8 * HEAD + col] =
                    make_float2(oc[rg][jn][2] * inv1, oc[rg][jn][3] * inv1);
            }
        }
    } else {
        __half* Op = gOp16 + (size_t)slot * 8192;
#pragma unroll
        for (int rg = 0; rg < 2; rg++) {
            const int row0 = m0w + rg * 16 + g;
            const int row1 = row0 + 8;
#pragma unroll
            for (int jn = 0; jn < 8; jn++) {
                int col = jn * 8 + 2 * tg;
                *(uint32_t*)&Op[row0 * 64 + col] = cvt2h(oc[rg][jn][0], oc[rg][jn][1]);
                *(uint32_t*)&Op[row1 * 64 + col] = cvt2h(oc[rg][jn][2], oc[rg][jn][3]);
            }
            if (tg == 0) {
                gLp[slot * 128 + row0] = lc[rg][0];
                gLp[slot * 128 + row1] = lc[rg][2];
            }
        }
    }
}

// ============================================================================
// Kernel 2b: combine partials + normalize, q >= 4 only.
// 448 CTAs (= 4 b x 28 q x 4 row-quarters) x 256 threads;
// thread = (row in quarter, 8-col strip).
// ============================================================================
__global__ __launch_bounds__(256) void attn_comb(float* __restrict__ out)
{
    const int bid = blockIdx.x;          // 0..447
    const int u   = bid >> 2;            // 0..111
    const int rq  = bid & 3;             // row quarter
    const int b   = u / 28;
    const int q   = 4 + (u % 28);
    const int tid = threadIdx.x;
    const int row = rq * 32 + (tid >> 3);   // 0..127
    const int col = (tid & 7) * 8;          // 0..56 step 8

    const int k    = q >> 2;
    const int nch  = k + 1;              // 2..8
    const int off0 = (k + 1) * (q - 2 * k);
    const int slot0 = b * 144 + off0;

    cudaGridDependencySynchronize();   // gOp16/gLp now valid

    float acc[8];
#pragma unroll
    for (int i = 0; i < 8; i++) acc[i] = 0.f;
    float lsum = 0.f;

    for (int c = 0; c < nch; c++) {
        const __half* Op = gOp16 + (size_t)(slot0 + c) * 8192 + row * 64 + col;
        uint4 v = *(const uint4*)Op;         // 8 halves
        lsum += gLp[(slot0 + c) * 128 + row];
        const uint32_t* w = &v.x;
#pragma unroll
        for (int qq = 0; qq < 4; qq++) {
            float2 f = __half22float2(*(const __half2*)&w[qq]);
            acc[2 * qq]     += f.x;
            acc[2 * qq + 1] += f.y;
        }
    }

    const float inv = 1.0f / lsum;
    float* dst = out + ((size_t)(b * SEQ + q * 128 + row)) * HEAD + col;
    *(float4*)&dst[0] = make_float4(acc[0] * inv, acc[1] * inv, acc[2] * inv, acc[3] * inv);
    *(float4*)&dst[4] = make_float4(acc[4] * inv, acc[5] * inv, acc[6] * inv, acc[7] * inv);
}

// ============================================================================
// launch (PDL-chained)
// ============================================================================
static inline void launch_pdl(const void* fn, dim3 grid, dim3 block, size_t smem,
                              void** args)
{
    cudaLaunchConfig_t cfg = {};
    cfg.gridDim = grid;
    cfg.blockDim = block;
    cfg.dynamicSmemBytes = smem;
    cudaLaunchAttribute attr[1];
    attr[0].id = cudaLaunchAttributeProgrammaticStreamSerialization;
    attr[0].val.programmaticStreamSerializationAllowed = 1;
    cfg.attrs = attr;
    cfg.numAttrs = 1;
    cudaLaunchKernelExC(&cfg, fn, args);
}

extern "C" void kernel_launch(void* const* d_in, const int* in_sizes, int n_in,
                              void* d_out, int out_size)
{
    const float* x  = (const float*)d_in[0];
    const float* Wk = (const float*)d_in[1];
    const float* Wq = (const float*)d_in[2];
    const float* Wv = (const float*)d_in[3];
    float* out = (float*)d_out;

    w16_kernel<<<192, 128>>>(Wk, Wq, Wv);

    static int smem_set = 0;
    if (!smem_set) {
        cudaFuncSetAttribute(proj_mma, cudaFuncAttributeMaxDynamicSharedMemorySize, PSMEM);
        smem_set = 1;
    }

    {
        void* args[] = { (void*)&x };
        launch_pdl((const void*)proj_mma, dim3(NTOK / 64), dim3(256), PSMEM, args);
    }
    {
        void* args[] = { (void*)&out };
        launch_pdl((const void*)attn_part, dim3(NUNITS), dim3(128), 0, args);
    }
    {
        void* args[] = { (void*)&out };
        launch_pdl((const void*)attn_comb, dim3(448), dim3(256), 0, args);
    }
}

// round 15
// speedup vs baseline: 1.1191x; 1.0803x over previous
#include <cuda_runtime.h>
#include <cuda_fp16.h>
#include <cstdint>

#define BATCH 4
#define SEQ   4096
#define EMBED 512
#define HEAD  64
#define NTOK  (BATCH * SEQ)
// C^-0.5 * log2(e): Q pre-scale so softmax uses raw ex2
#define QSC2  (0.04419417382415922f * 1.4426950408889634f)

#define NUNITS 320          // split-K work units (80 per batch), 128-row q-tiles
#define NEG_INF __int_as_float(0xff800000)
#define ONES16  0x3C003C00u // (1.0h, 1.0h)

// ---------------- scratch (device globals) ----------------
__device__ __half gK16[NTOK * HEAD];   // [t][h]
__device__ __half gQ16[NTOK * HEAD];   // [t][h], pre-scaled by QSC2
__device__ __half gV16[NTOK * HEAD];   // [t][h]
__device__ __half gW16[192 * EMBED];   // [Wk;Wq;Wv] rows, fp16
__device__ __half gOp16[NUNITS * 128 * 64]; // partial O (unnormalized, fp16)
__device__ float  gLp[NUNITS * 128];        // partial l (fp32)

// ---------------- helpers ----------------
__device__ __forceinline__ uint32_t smem_u32(const void* p) {
    uint32_t a;
    asm("{ .reg .u64 t; cvta.to.shared.u64 t, %1; cvt.u32.u64 %0, t; }" : "=r"(a) : "l"(p));
    return a;
}
__device__ __forceinline__ void ldsm4(uint32_t* r, uint32_t addr) {
    asm volatile("ldmatrix.sync.aligned.m8n8.x4.shared.b16 {%0,%1,%2,%3}, [%4];"
                 : "=r"(r[0]), "=r"(r[1]), "=r"(r[2]), "=r"(r[3]) : "r"(addr));
}
__device__ __forceinline__ void ldsm4t(uint32_t* r, uint32_t addr) {
    asm volatile("ldmatrix.sync.aligned.m8n8.x4.trans.shared.b16 {%0,%1,%2,%3}, [%4];"
                 : "=r"(r[0]), "=r"(r[1]), "=r"(r[2]), "=r"(r[3]) : "r"(addr));
}
__device__ __forceinline__ void mma16816(float* c, const uint32_t* a, uint32_t b0, uint32_t b1) {
    asm volatile(
        "mma.sync.aligned.m16n8k16.row.col.f32.f16.f16.f32 "
        "{%0,%1,%2,%3}, {%4,%5,%6,%7}, {%8,%9}, {%0,%1,%2,%3};"
        : "+f"(c[0]), "+f"(c[1]), "+f"(c[2]), "+f"(c[3])
        : "r"(a[0]), "r"(a[1]), "r"(a[2]), "r"(a[3]), "r"(b0), "r"(b1));
}
// single-instruction fp32x2 -> half2 pack (low = a, high = b)
__device__ __forceinline__ uint32_t cvt2h(float a, float b) {
    uint32_t r;
    asm("cvt.rn.f16x2.f32 %0, %1, %2;" : "=r"(r) : "f"(b), "f"(a));
    return r;
}
__device__ __forceinline__ float ex2f(float x) {
    float y;
    asm("ex2.approx.f32 %0, %1;" : "=f"(y) : "f"(x));
    return y;
}
__device__ __forceinline__ void cp16(uint32_t dst, const void* src) {
    asm volatile("cp.async.cg.shared.global [%0], [%1], 16;"
                 :: "r"(dst), "l"(__cvta_generic_to_global(src)) : "memory");
}
#define CP_COMMIT() asm volatile("cp.async.commit_group;" ::: "memory")
#define CP_WAIT0()  asm volatile("cp.async.wait_group 0;" ::: "memory")

// ============================================================================
// Kernel 0: weights fp32 -> fp16, stacked [Wk;Wq;Wv] = [192][512], 4/thread
// ============================================================================
__global__ __launch_bounds__(128) void w16_kernel(
    const float* __restrict__ Wk, const float* __restrict__ Wq,
    const float* __restrict__ Wv)
{
    int i4 = (blockIdx.x * 128 + threadIdx.x) * 4;   // 0..98300
    const float* src;
    int off;
    if (i4 < 64 * EMBED)       { src = Wk; off = i4; }
    else if (i4 < 128 * EMBED) { src = Wq; off = i4 - 64 * EMBED; }
    else                       { src = Wv; off = i4 - 128 * EMBED; }
    float4 f = *(const float4*)&src[off];
    *(uint2*)&gW16[i4] = make_uint2(cvt2h(f.x, f.y), cvt2h(f.z, f.w));
}

// ============================================================================
// Kernel 1: KQV projection via fp16 mma.sync (W via cp.async, x converted
// inline). PDL: x chunk-0 staged before griddepsync. Double-buffered.
// ============================================================================
#define PX(s) ((s) * 8192)             // 2 x 8KB x buffers
#define PW(s) (16384 + (s) * 24576)    // 2 x 24KB W buffers
#define PSMEM 65536

__global__ __launch_bounds__(256) void proj_mma(const float* __restrict__ x)
{
    extern __shared__ __align__(16) uint8_t smem[];
    const uint32_t sb = smem_u32(smem);

    const int tid  = threadIdx.x;
    const int wid  = tid >> 5;
    const int lane = tid & 31;
    const int wm   = (wid & 3) * 16;    // warp row base
    const int h    = wid >> 2;          // warp n-half (0: cols 0-95, 1: 96-191)
    const int g    = lane >> 2;
    const int tg   = lane & 3;
    const int mblk = blockIdx.x * 64;

    float c[12][4];
#pragma unroll
    for (int j = 0; j < 12; j++)
#pragma unroll
        for (int q = 0; q < 4; q++) c[j][q] = 0.f;

#define STAGE_W(kc, s)                                                              \
    do {                                                                            \
        _Pragma("unroll")                                                           \
        for (int it = 0; it < 6; it++) {                                            \
            int idx = tid + it * 256;          /* 0..1535 uint4s */                 \
            int r = idx >> 3, u = idx & 7;                                          \
            uint32_t dst = r * 128 + ((u * 16) ^ ((r & 7) << 4));                   \
            cp16(sb + PW(s) + dst, &gW16[(size_t)r * EMBED + (kc) * 64 + u * 8]);   \
        }                                                                           \
    } while (0)

#define STAGE_X(kc, s)                                                              \
    do {                                                                            \
        _Pragma("unroll")                                                           \
        for (int it = 0; it < 4; it++) {                                            \
            int idx = tid + it * 256;          /* 0..1023 float4s */                \
            int r = idx >> 4, c4 = idx & 15;                                        \
            float4 f = *(const float4*)&x[(size_t)(mblk + r) * EMBED + (kc) * 64 + c4 * 4]; \
            uint32_t dst = r * 128 + ((c4 * 8) ^ ((r & 7) << 4));                   \
            *(uint2*)(smem + PX(s) + dst) =                                         \
                make_uint2(cvt2h(f.x, f.y), cvt2h(f.z, f.w));                       \
        }                                                                           \
    } while (0)

    // x chunk 0 is independent of w16's output -> stage it before the PDL sync
    STAGE_X(0, 0);
    cudaGridDependencySynchronize();   // gW16 now valid
    STAGE_W(0, 0);
    CP_COMMIT();
    CP_WAIT0();
    __syncthreads();

    for (int kc = 0; kc < 8; kc++) {
        const int s = kc & 1;
        if (kc < 7) {
            STAGE_W(kc + 1, s ^ 1);
            CP_COMMIT();
            STAGE_X(kc + 1, s ^ 1);
        }

#pragma unroll
        for (int ks = 0; ks < 4; ks++) {
            uint32_t ah[4];
            int arow = wm + (lane & 15);
            uint32_t abyte = (uint32_t)((ks * 32 + (lane >> 4) * 16) ^ ((arow & 7) << 4));
            ldsm4(ah, sb + PX(s) + arow * 128 + abyte);
#pragma unroll
            for (int jj = 0; jj < 6; jj++) {
                uint32_t b[4];
                int brow = h * 96 + jj * 16 + (lane & 7) + ((lane >> 4) << 3);
                uint32_t bby = (uint32_t)((ks * 32 + ((lane >> 3) & 1) * 16) ^ ((brow & 7) << 4));
                ldsm4(b, sb + PW(s) + brow * 128 + bby);
                mma16816(c[2 * jj],     ah, b[0], b[1]);
                mma16816(c[2 * jj + 1], ah, b[2], b[3]);
            }
        }
        if (kc < 7) CP_WAIT0();
        __syncthreads();
    }
#undef STAGE_W
#undef STAGE_X

    const int m0 = mblk + wm + g;
#pragma unroll
    for (int j = 0; j < 12; j++) {
        int col = h * 96 + j * 8 + 2 * tg;
        if (col < 64) {
            *(uint32_t*)&gK16[(size_t)m0 * HEAD + col]       = cvt2h(c[j][0], c[j][1]);
            *(uint32_t*)&gK16[(size_t)(m0 + 8) * HEAD + col] = cvt2h(c[j][2], c[j][3]);
        } else if (col < 128) {
            int hh = col - 64;
            *(uint32_t*)&gQ16[(size_t)m0 * HEAD + hh]       = cvt2h(c[j][0] * QSC2, c[j][1] * QSC2);
            *(uint32_t*)&gQ16[(size_t)(m0 + 8) * HEAD + hh] = cvt2h(c[j][2] * QSC2, c[j][3] * QSC2);
        } else {
            int hh = col - 128;
            *(uint32_t*)&gV16[(size_t)m0 * HEAD + hh]       = cvt2h(c[j][0], c[j][1]);
            *(uint32_t*)&gV16[(size_t)(m0 + 8) * HEAD + hh] = cvt2h(c[j][2], c[j][3]);
        }
    }
}

// ============================================================================
// Kernel 2a: attention pass 1 (split-K), 128-row q-tiles, warp = 32 rows
// (2 row-groups: each ldsm'd K/V B-frag feeds 2x MMA work). Register P,
// l via MMA. Chunk = 16 key tiles -> half the partial traffic of R14.
//   rank r (0..79 per batch): r<8 -> q=r single-chunk (direct write);
//   r in [8,24):  q=8+(r-8)/2,  ch=(r-8)%2
//   r in [24,48): q=16+(r-24)/3, ch=(r-24)%3
//   r in [48,80): q=24+(r-48)/4, ch=(r-48)%4
// Launch order: descending r, batch-interleaved (big units first).
// ============================================================================
#define AQS  0            // 16KB Q (128 rows)
#define AK0  16384        // 2x8KB K
#define AV0  32768        // 2x8KB V
#define ASMEM 49152

__global__ __launch_bounds__(128) void attn_part(float* __restrict__ out)
{
    __shared__ __align__(16) uint8_t smem[ASMEM];
    const uint32_t sb = smem_u32(smem);

    // descending work order, batch-interleaved
    const int u = (NUNITS - 1) - blockIdx.x;
    const int r = u >> 2;                // rank 0..79
    const int b = u & 3;
    int q, ch;
    if (r < 8)       { q = r;                ch = 0; }
    else if (r < 24) { q = 8  + (r - 8) / 2;  ch = (r - 8) % 2; }
    else if (r < 48) { q = 16 + (r - 24) / 3; ch = (r - 24) % 3; }
    else             { q = 24 + (r - 48) / 4; ch = (r - 48) % 4; }
    const int kt0 = ch * 16;
    const int ktop = 2 * q + 2;
    const int kt1 = (kt0 + 16 < ktop) ? (kt0 + 16) : ktop;
    const int nit = kt1 - kt0;
    const bool single = (r < 8);
    const int slot = b * 80 + r;

    const int tid  = threadIdx.x;
    const int wid  = tid >> 5;
    const int lane = tid & 31;
    const int m0w  = wid * 32;           // warp's 32-row base
    const int g    = lane >> 2;
    const int tg   = lane & 3;

    const __half* __restrict__ Qg = gQ16 + (size_t)(b * SEQ + q * 128) * HEAD;
    const __half* __restrict__ Kb = gK16 + (size_t)(b * SEQ) * HEAD;
    const __half* __restrict__ Vb = gV16 + (size_t)(b * SEQ) * HEAD;

    cudaGridDependencySynchronize();   // gQ16/gK16/gV16 now valid

    // stage Q (128 rows = 1024 uint4) + first K/V tile (512 uint4 each)
#pragma unroll
    for (int it = 0; it < 8; it++) {
        int idx = tid + it * 128;          // 0..1023
        int rw = idx >> 3, uu = idx & 7;
        uint32_t dst = rw * 128 + ((uu * 16) ^ ((rw & 7) << 4));
        cp16(sb + AQS + dst, &Qg[rw * HEAD + uu * 8]);
    }
#pragma unroll
    for (int it = 0; it < 4; it++) {
        int idx = tid + it * 128;          // 0..511
        int rw = idx >> 3, uu = idx & 7;
        uint32_t dst = rw * 128 + ((uu * 16) ^ ((rw & 7) << 4));
        cp16(sb + AK0 + dst, &Kb[(size_t)(kt0 * 64 + rw) * HEAD + uu * 8]);
        cp16(sb + AV0 + dst, &Vb[(size_t)(kt0 * 64 + rw) * HEAD + uu * 8]);
    }
    CP_COMMIT();
    CP_WAIT0();
    __syncthreads();

    // Q A-frags for both row-groups, loaded once
    uint32_t qa[2][4][4];
#pragma unroll
    for (int rg = 0; rg < 2; rg++) {
        int arow = m0w + rg * 16 + (lane & 15);
#pragma unroll
        for (int k4 = 0; k4 < 4; k4++) {
            uint32_t abyte = (uint32_t)((k4 * 32 + (lane >> 4) * 16) ^ ((arow & 7) << 4));
            ldsm4(qa[rg][k4], sb + AQS + arow * 128 + abyte);
        }
    }

    float oc[2][8][4];
#pragma unroll
    for (int rg = 0; rg < 2; rg++)
#pragma unroll
        for (int j = 0; j < 8; j++)
#pragma unroll
            for (int qq = 0; qq < 4; qq++) oc[rg][j][qq] = 0.f;
    float lc[2][4] = {{0.f,0.f,0.f,0.f},{0.f,0.f,0.f,0.f}};

    int stage = 0;
    for (int i = 0; i < nit; i++) {
        const int kt = kt0 + i;
        if (i + 1 < nit) {
            uint32_t kbuf = AK0 + ((i + 1) & 1) * 8192;
            uint32_t vbuf = AV0 + ((i + 1) & 1) * 8192;
            const __half* Kg = Kb + (size_t)(kt + 1) * 64 * HEAD;
            const __half* Vg = Vb + (size_t)(kt + 1) * 64 * HEAD;
#pragma unroll
            for (int it = 0; it < 4; it++) {
                int idx = tid + it * 128;
                int rw = idx >> 3, uu = idx & 7;
                uint32_t dst = rw * 128 + ((uu * 16) ^ ((rw & 7) << 4));
                cp16(sb + kbuf + dst, &Kg[rw * HEAD + uu * 8]);
                cp16(sb + vbuf + dst, &Vg[rw * HEAD + uu * 8]);
            }
            CP_COMMIT();
        }

        const uint32_t kbase = sb + AK0 + stage * 8192;
        const uint32_t vbase = sb + AV0 + stage * 8192;

        // ---- MMA1: S = Q @ K^T (both row-groups share each B-frag) ----
        float sc[2][8][4];
#pragma unroll
        for (int rg = 0; rg < 2; rg++)
#pragma unroll
            for (int j = 0; j < 8; j++)
#pragma unroll
                for (int qq = 0; qq < 4; qq++) sc[rg][j][qq] = 0.f;
#pragma unroll
        for (int jj = 0; jj < 4; jj++) {
            int brow = jj * 16 + (lane & 7) + ((lane >> 4) << 3);
#pragma unroll
            for (int k4 = 0; k4 < 4; k4++) {
                uint32_t bby = (uint32_t)((k4 * 32 + ((lane >> 3) & 1) * 16) ^ ((brow & 7) << 4));
                uint32_t bk[4];
                ldsm4(bk, kbase + brow * 128 + bby);
#pragma unroll
                for (int rg = 0; rg < 2; rg++) {
                    mma16816(sc[rg][2 * jj],     qa[rg][k4], bk[0], bk[1]);
                    mma16816(sc[rg][2 * jj + 1], qa[rg][k4], bk[2], bk[3]);
                }
            }
        }

        // ---- causal mask on overlapping tiles (global indices) ----
        if (kt >= 2 * q) {
            const int kb = kt * 64;
            const int qb = q * 128;
#pragma unroll
            for (int rg = 0; rg < 2; rg++) {
                const int qr0 = qb + m0w + rg * 16 + g;
                const int qr1 = qr0 + 8;
#pragma unroll
                for (int jn = 0; jn < 8; jn++) {
                    int kc = kb + jn * 8 + 2 * tg;
                    if (kc     > qr0) sc[rg][jn][0] = NEG_INF;
                    if (kc + 1 > qr0) sc[rg][jn][1] = NEG_INF;
                    if (kc     > qr1) sc[rg][jn][2] = NEG_INF;
                    if (kc + 1 > qr1) sc[rg][jn][3] = NEG_INF;
                }
            }
        }

        // ---- exp2 + pack into MMA2 A-frags; l via MMA ----
        uint32_t pfr[2][4][4];
#pragma unroll
        for (int rg = 0; rg < 2; rg++)
#pragma unroll
            for (int k4 = 0; k4 < 4; k4++) {
                pfr[rg][k4][0] = cvt2h(ex2f(sc[rg][2 * k4][0]),     ex2f(sc[rg][2 * k4][1]));
                pfr[rg][k4][1] = cvt2h(ex2f(sc[rg][2 * k4][2]),     ex2f(sc[rg][2 * k4][3]));
                pfr[rg][k4][2] = cvt2h(ex2f(sc[rg][2 * k4 + 1][0]), ex2f(sc[rg][2 * k4 + 1][1]));
                pfr[rg][k4][3] = cvt2h(ex2f(sc[rg][2 * k4 + 1][2]), ex2f(sc[rg][2 * k4 + 1][3]));
                mma16816(lc[rg], pfr[rg][k4], ONES16, ONES16);
            }

        // ---- MMA2: O += P @ V (both row-groups share each B-frag) ----
#pragma unroll
        for (int jj = 0; jj < 4; jj++) {
#pragma unroll
            for (int k4 = 0; k4 < 4; k4++) {
                int krow = k4 * 16 + (lane & 7) + (((lane >> 3) & 1) << 3);
                uint32_t vby = (uint32_t)(((jj * 16 + ((lane >> 4) << 3)) * 2) ^ ((krow & 7) << 4));
                uint32_t bv[4];
                ldsm4t(bv, vbase + krow * 128 + vby);
#pragma unroll
                for (int rg = 0; rg < 2; rg++) {
                    mma16816(oc[rg][2 * jj],     pfr[rg][k4], bv[0], bv[1]);
                    mma16816(oc[rg][2 * jj + 1], pfr[rg][k4], bv[2], bv[3]);
                }
            }
        }

        if (i + 1 < nit) {
            CP_WAIT0();
            __syncthreads();
        }
        stage ^= 1;
    }

    if (single) {
#pragma unroll
        for (int rg = 0; rg < 2; rg++) {
            const float inv0 = 1.0f / lc[rg][0];
            const float inv1 = 1.0f / lc[rg][2];
            const int row0 = m0w + rg * 16 + g;
            const size_t ro = (size_t)(b * SEQ + q * 128 + row0) * HEAD;
#pragma unroll
            for (int jn = 0; jn < 8; jn++) {
                int col = jn * 8 + 2 * tg;
                *(float2*)&out[ro + col] =
                    make_float2(oc[rg][jn][0] * inv0, oc[rg][jn][1] * inv0);
                *(float2*)&out[ro + 8 * HEAD + col] =
                    make_float2(oc[rg][jn][2] * inv1, oc[rg][jn][3] * inv1);
            }
        }
    } else {
        __half* Op = gOp16 + (size_t)slot * 8192;
#pragma unroll
        for (int rg = 0; rg < 2; rg++) {
            const int row0 = m0w + rg * 16 + g;
            const int row1 = row0 + 8;
#pragma unroll
            for (int jn = 0; jn < 8; jn++) {
                int col = jn * 8 + 2 * tg;
                *(uint32_t*)&Op[row0 * 64 + col] = cvt2h(oc[rg][jn][0], oc[rg][jn][1]);
                *(uint32_t*)&Op[row1 * 64 + col] = cvt2h(oc[rg][jn][2], oc[rg][jn][3]);
            }
            if (tg == 0) {
                gLp[slot * 128 + row0] = lc[rg][0];
                gLp[slot * 128 + row1] = lc[rg][2];
            }
        }
    }
}

// ============================================================================
// Kernel 2b: combine partials + normalize, q >= 8 only.
// 384 CTAs (= 4 b x 24 q x 4 row-quarters) x 256 threads;
// thread = (row in quarter, 8-col strip). nch = (q>>3)+1 in {2,3,4}.
// ============================================================================
__global__ __launch_bounds__(256) void attn_comb(float* __restrict__ out)
{
    const int bid = blockIdx.x;          // 0..383
    const int u   = bid >> 2;            // 0..95
    const int rq  = bid & 3;             // row quarter
    const int b   = u / 24;
    const int q   = 8 + (u % 24);
    const int tid = threadIdx.x;
    const int row = rq * 32 + (tid >> 3);   // 0..127
    const int col = (tid & 7) * 8;          // 0..56 step 8

    const int nch = (q >> 3) + 1;        // 2..4
    int off0;
    if (q < 16)      off0 = 8  + (q - 8)  * 2;
    else if (q < 24) off0 = 24 + (q - 16) * 3;
    else             off0 = 48 + (q - 24) * 4;
    const int slot0 = b * 80 + off0;

    cudaGridDependencySynchronize();   // gOp16/gLp now valid

    float acc[8];
#pragma unroll
    for (int i = 0; i < 8; i++) acc[i] = 0.f;
    float lsum = 0.f;

    for (int c = 0; c < nch; c++) {
        const __half* Op = gOp16 + (size_t)(slot0 + c) * 8192 + row * 64 + col;
        uint4 v = *(const uint4*)Op;         // 8 halves
        lsum += gLp[(slot0 + c) * 128 + row];
        const uint32_t* w = &v.x;
#pragma unroll
        for (int qq = 0; qq < 4; qq++) {
            float2 f = __half22float2(*(const __half2*)&w[qq]);
            acc[2 * qq]     += f.x;
            acc[2 * qq + 1] += f.y;
        }
    }

    const float inv = 1.0f / lsum;
    float* dst = out + ((size_t)(b * SEQ + q * 128 + row)) * HEAD + col;
    *(float4*)&dst[0] = make_float4(acc[0] * inv, acc[1] * inv, acc[2] * inv, acc[3] * inv);
    *(float4*)&dst[4] = make_float4(acc[4] * inv, acc[5] * inv, acc[6] * inv, acc[7] * inv);
}

// ============================================================================
// launch (PDL-chained)
// ============================================================================
static inline void launch_pdl(const void* fn, dim3 grid, dim3 block, size_t smem,
                              void** args)
{
    cudaLaunchConfig_t cfg = {};
    cfg.gridDim = grid;
    cfg.blockDim = block;
    cfg.dynamicSmemBytes = smem;
    cudaLaunchAttribute attr[1];
    attr[0].id = cudaLaunchAttributeProgrammaticStreamSerialization;
    attr[0].val.programmaticStreamSerializationAllowed = 1;
    cfg.attrs = attr;
    cfg.numAttrs = 1;
    cudaLaunchKernelExC(&cfg, fn, args);
}

extern "C" void kernel_launch(void* const* d_in, const int* in_sizes, int n_in,
                              void* d_out, int out_size)
{
    const float* x  = (const float*)d_in[0];
    const float* Wk = (const float*)d_in[1];
    const float* Wq = (const float*)d_in[2];
    const float* Wv = (const float*)d_in[3];
    float* out = (float*)d_out;

    w16_kernel<<<192, 128>>>(Wk, Wq, Wv);

    static int smem_set = 0;
    if (!smem_set) {
        cudaFuncSetAttribute(proj_mma, cudaFuncAttributeMaxDynamicSharedMemorySize, PSMEM);
        smem_set = 1;
    }

    {
        void* args[] = { (void*)&x };
        launch_pdl((const void*)proj_mma, dim3(NTOK / 64), dim3(256), PSMEM, args);
    }
    {
        void* args[] = { (void*)&out };
        launch_pdl((const void*)attn_part, dim3(NUNITS), dim3(128), 0, args);
    }
    {
        void* args[] = { (void*)&out };
        launch_pdl((const void*)attn_comb, dim3(384), dim3(256), 0, args);
    }
}